// round 8
// baseline (speedup 1.0000x reference)
#include <cuda_runtime.h>
#include <cuda_bf16.h>
#include <cstdint>

// ============================================================================
// CAAN rank-gated attention (sm_100 base: mma.sync bf16 + cp.async):
//   Sh/Sl = bf16 split of S; f[i] = S[i].u + c (fused into convS)
//   Q,K   = S Wq^T/Wk^T via 3-product bf16-split HMMA, re-split to bf16 hi/lo
//   gate2[d] = log2(e)/sqrt(128) * sigmoid(rank_emb[d].wL+bL)
//   p_ij = exp2( gate2[|ri-rj|/4] * (q_i.k_j) )   (no-max softmax; |arg| small)
//   out_i = sigmoid( (sum_j p f_j)/(sum_j p) + wf_b )
// attn overlap: double acc sets; epilogue(kt-1) interleaved into MMA(kt)
// dispatch so ALU/MUFU work rides the tensor-pipe pacing gaps.
// ============================================================================

#define N_ASSETS 4096
#define D_MODEL  512
#define DK       128
#define NUM_EMB  1024
#define NCHUNK   4
#define KEYS_PER_CHUNK (N_ASSETS / NCHUNK)
#define SCORE_SCALE 0.08838834764831845f     // 1/sqrt(128)
#define GATE_MUL    0.1275174677682657f      // SCORE_SCALE * log2(e)

typedef unsigned long long ull;

// --------------------------- scratch (no allocs) ----------------------------
__device__ __align__(16) __nv_bfloat16 d_Sh[N_ASSETS * D_MODEL];
__device__ __align__(16) __nv_bfloat16 d_Sl[N_ASSETS * D_MODEL];
__device__ __align__(16) __nv_bfloat16 d_Wh[256 * D_MODEL];   // rows 0-127 Wq, 128-255 Wk
__device__ __align__(16) __nv_bfloat16 d_Wl[256 * D_MODEL];
__device__ __align__(16) __nv_bfloat16 d_Qh[N_ASSETS * DK];
__device__ __align__(16) __nv_bfloat16 d_Ql[N_ASSETS * DK];
__device__ __align__(16) __nv_bfloat16 d_Kh[N_ASSETS * DK];
__device__ __align__(16) __nv_bfloat16 d_Kl[N_ASSETS * DK];
__device__ float d_f[N_ASSETS];
__device__ float d_u[D_MODEL + 1];
__device__ float d_gate[NUM_EMB];            // premultiplied by GATE_MUL
__device__ float d_pl[NCHUNK * N_ASSETS];
__device__ float d_pw[NCHUNK * N_ASSETS];

// --------------------------- mma/ldsm/cp.async helpers -----------------------
__device__ __forceinline__ uint32_t smem_u32(const void* p) {
    uint32_t a;
    asm("{ .reg .u64 t; cvta.to.shared.u64 t, %1; cvt.u32.u64 %0, t; }"
        : "=r"(a) : "l"(p));
    return a;
}
__device__ __forceinline__ void ldsm4(uint32_t* r, uint32_t addr) {
    asm volatile("ldmatrix.sync.aligned.m8n8.x4.shared.b16 {%0,%1,%2,%3}, [%4];"
                 : "=r"(r[0]), "=r"(r[1]), "=r"(r[2]), "=r"(r[3]) : "r"(addr));
}
__device__ __forceinline__ void mma_bf16(float* c, const uint32_t* a, const uint32_t* b) {
    asm volatile(
        "mma.sync.aligned.m16n8k16.row.col.f32.bf16.bf16.f32 "
        "{%0,%1,%2,%3}, {%4,%5,%6,%7}, {%8,%9}, {%0,%1,%2,%3};"
        : "+f"(c[0]), "+f"(c[1]), "+f"(c[2]), "+f"(c[3])
        : "r"(a[0]), "r"(a[1]), "r"(a[2]), "r"(a[3]), "r"(b[0]), "r"(b[1]));
}
__device__ __forceinline__ void cp16(uint32_t dst, const void* src) {
    asm volatile("cp.async.cg.shared.global [%0], [%1], 16;" :: "r"(dst), "l"(src));
}
__device__ __forceinline__ void cp4(uint32_t dst, const void* src) {
    asm volatile("cp.async.ca.shared.global [%0], [%1], 4;" :: "r"(dst), "l"(src));
}
#define CP_COMMIT() asm volatile("cp.async.commit_group;" ::: "memory")
#define CP_WAIT0()  asm volatile("cp.async.wait_group 0;" ::: "memory")
#define CP_WAIT1()  asm volatile("cp.async.wait_group 1;" ::: "memory")

// XOR swizzle of 16B-chunk index within a 256B row (16 chunks)
__device__ __forceinline__ int swz(int chunk, int row) {
    return (chunk & 8) | ((chunk ^ row) & 7);
}
__device__ __forceinline__ void bf16_split(float v, __nv_bfloat16& h, __nv_bfloat16& l) {
    h = __float2bfloat16(v);
    l = __float2bfloat16(v - __bfloat162float(h));
}

// ============================================================================
// prep: gate (b 0-3), u (b 4-19), c (b 20), W bf16 split (b 21-84)
// ============================================================================
__global__ void prep_kernel(const float* __restrict__ rank_emb,
                            const float* __restrict__ wL_w,
                            const float* __restrict__ wL_b,
                            const float* __restrict__ Wv_w,
                            const float* __restrict__ wf_w,
                            const float* __restrict__ Wv_b,
                            const float* __restrict__ Wq_w,
                            const float* __restrict__ Wk_w) {
    int b = blockIdx.x, t = threadIdx.x;
    if (b < 4) {
        int d = b * 256 + t;
        float s = wL_b[0];
        #pragma unroll 8
        for (int e = 0; e < 32; e++) s += rank_emb[d * 32 + e] * wL_w[e];
        d_gate[d] = GATE_MUL / (1.0f + __expf(-s));
    } else if (b < 20) {
        int b2 = b - 4;
        int mloc = t & 31, oo = t >> 5;
        int m = b2 * 32 + mloc;
        float s = 0.f;
        #pragma unroll 4
        for (int o = oo; o < D_MODEL; o += 8) s += Wv_w[o * D_MODEL + m] * wf_w[o];
        __shared__ float red[256];
        red[t] = s; __syncthreads();
        if (t < 32) {
            float x = red[t];
            #pragma unroll
            for (int i = 1; i < 8; i++) x += red[t + 32 * i];
            d_u[m] = x;
        }
    } else if (b == 20) {
        __shared__ float red[256];
        float s = 0.f;
        for (int o = t; o < D_MODEL; o += 256) s += wf_w[o] * Wv_b[o];
        red[t] = s; __syncthreads();
        for (int st = 128; st > 0; st >>= 1) {
            if (t < st) red[t] += red[t + st];
            __syncthreads();
        }
        if (t == 0) d_u[D_MODEL] = red[0];
    } else {
        int g0 = (b - 21) * 2048 + t * 8;
        #pragma unroll
        for (int j = 0; j < 2; j++) {
            float4 v = (g0 + 4 * j < 65536)
                ? *(const float4*)(Wq_w + g0 + 4 * j)
                : *(const float4*)(Wk_w + g0 + 4 * j - 65536);
            float vv[4] = {v.x, v.y, v.z, v.w};
            #pragma unroll
            for (int e = 0; e < 4; e++) {
                __nv_bfloat16 h, l;
                bf16_split(vv[e], h, l);
                d_Wh[g0 + 4 * j + e] = h;
                d_Wl[g0 + 4 * j + e] = l;
            }
        }
    }
}

// ============================================================================
// convS: split S into bf16 hi/lo AND compute f[i] = S[i].u + c (one pass)
// ============================================================================
__global__ void __launch_bounds__(256) convS_kernel(const float* __restrict__ S) {
    __shared__ float u_s[D_MODEL];
    int tid = threadIdx.x, w = tid >> 5, lane = tid & 31;
    #pragma unroll
    for (int t = 0; t < 2; t++) u_s[tid + 256 * t] = d_u[tid + 256 * t];
    __syncthreads();
    float c = d_u[D_MODEL];

    int rbase = blockIdx.x * 32 + w * 4;
    #pragma unroll
    for (int rr = 0; rr < 4; rr++) {
        int row = rbase + rr;
        const float2* src = (const float2*)(S + (size_t)row * D_MODEL);
        __nv_bfloat162* dh = (__nv_bfloat162*)(d_Sh + (size_t)row * D_MODEL);
        __nv_bfloat162* dl = (__nv_bfloat162*)(d_Sl + (size_t)row * D_MODEL);
        float s = 0.f;
        #pragma unroll
        for (int t = 0; t < 8; t++) {
            int e2 = lane + 32 * t;
            float2 v = src[e2];
            s += v.x * u_s[2 * e2] + v.y * u_s[2 * e2 + 1];
            __nv_bfloat16 h0, l0, h1, l1;
            bf16_split(v.x, h0, l0);
            bf16_split(v.y, h1, l1);
            dh[e2] = __nv_bfloat162(h0, h1);
            dl[e2] = __nv_bfloat162(l0, l1);
        }
        #pragma unroll
        for (int st = 16; st > 0; st >>= 1)
            s += __shfl_xor_sync(0xffffffffu, s, st);
        if (lane == 0) d_f[row] = s + c;
    }
}

// ============================================================================
// proj_mma: Q/K = S @ W^T + b via 3-product bf16 HMMA, double-buffered stages.
// grid (64 M-tiles of 64 rows, 2 = {Q,K}), 256 thr = 8 warps (2M x 4N).
// ============================================================================
#define PJ_BIAS 0           // 512B
#define PJ_STG  1024        // stage stride 98304: SH 16K | SL 16K | WH 32K | WL 32K
#define PJ_SH   0
#define PJ_SL   16384
#define PJ_WH   32768
#define PJ_WL   65536
#define PJ_TOTAL (1024 + 2 * 98304)

__device__ __forceinline__ void pj_copy_stage(uint32_t stg, int mbase, int by, int kc) {
    int tid = threadIdx.x;
    // S: 64 rows x 128 cols hi+lo (1024 chunks each)
    #pragma unroll
    for (int i = 0; i < 4; i++) {
        int idx = tid + 256 * i;
        int row = idx >> 4, c = idx & 15;
        const __nv_bfloat16* gh = d_Sh + (size_t)(mbase + row) * D_MODEL + kc * 128 + c * 8;
        cp16(stg + PJ_SH + row * 256 + swz(c, row) * 16, gh);
        const __nv_bfloat16* gl = d_Sl + (size_t)(mbase + row) * D_MODEL + kc * 128 + c * 8;
        cp16(stg + PJ_SL + row * 256 + swz(c, row) * 16, gl);
    }
    // W: 128 rows x 128 cols hi+lo (2048 chunks each)
    #pragma unroll
    for (int i = 0; i < 8; i++) {
        int idx = tid + 256 * i;
        int row = idx >> 4, c = idx & 15;
        const __nv_bfloat16* gh = d_Wh + (size_t)(by * 128 + row) * D_MODEL + kc * 128 + c * 8;
        cp16(stg + PJ_WH + row * 256 + swz(c, row) * 16, gh);
        const __nv_bfloat16* gl = d_Wl + (size_t)(by * 128 + row) * D_MODEL + kc * 128 + c * 8;
        cp16(stg + PJ_WL + row * 256 + swz(c, row) * 16, gl);
    }
}

__global__ void __launch_bounds__(256, 1) proj_mma_kernel(
    const float* __restrict__ Wq_b, const float* __restrict__ Wk_b) {
    extern __shared__ __align__(1024) char smem[];
    uint32_t sb = smem_u32(smem);
    float* bias_s = (float*)(smem + PJ_BIAS);

    int tid = threadIdx.x;
    int w = tid >> 5, lane = tid & 31;
    int wm = w >> 2, wn = w & 3;
    int mbase = blockIdx.x * 64;
    int by = blockIdx.y;                 // 0 = Q, 1 = K

    if (tid < 128) bias_s[tid] = (by ? Wk_b : Wq_b)[tid];

    float acc[2][4][4];
    #pragma unroll
    for (int mi = 0; mi < 2; mi++)
        #pragma unroll
        for (int nf = 0; nf < 4; nf++)
            #pragma unroll
            for (int e = 0; e < 4; e++) acc[mi][nf][e] = 0.f;

    int a_row  = lane & 15, a_hi = lane >> 4;
    int b_nloc = (lane & 7) | ((lane >> 1) & 8);
    int b_hi   = (lane >> 3) & 1;

    pj_copy_stage(sb + PJ_STG, mbase, by, 0);
    CP_COMMIT();

    for (int kc = 0; kc < 4; kc++) {
        uint32_t stg = sb + PJ_STG + (kc & 1) * 98304;
        if (kc < 3) {
            pj_copy_stage(sb + PJ_STG + ((kc + 1) & 1) * 98304, mbase, by, kc + 1);
            CP_COMMIT();
            CP_WAIT1();
        } else {
            CP_WAIT0();
        }
        __syncthreads();

        #pragma unroll
        for (int ks = 0; ks < 8; ks++) {
            uint32_t Bh[2][4], Bl[2][4];
            int cB = 2 * ks + b_hi;
            #pragma unroll
            for (int np = 0; np < 2; np++) {
                int nrow = wn * 32 + np * 16 + b_nloc;
                uint32_t off = nrow * 256 + swz(cB, nrow) * 16;
                ldsm4(Bh[np], stg + PJ_WH + off);
                ldsm4(Bl[np], stg + PJ_WL + off);
            }
            #pragma unroll
            for (int mi = 0; mi < 2; mi++) {
                uint32_t Ah[4], Al[4];
                int qrow = wm * 32 + mi * 16 + a_row;
                int cA = 2 * ks + a_hi;
                uint32_t off = qrow * 256 + swz(cA, qrow) * 16;
                ldsm4(Ah, stg + PJ_SH + off);
                ldsm4(Al, stg + PJ_SL + off);
                #pragma unroll
                for (int nf = 0; nf < 4; nf++) {
                    float* cc = acc[mi][nf];
                    const uint32_t* bh = &Bh[nf >> 1][(nf & 1) * 2];
                    const uint32_t* bl = &Bl[nf >> 1][(nf & 1) * 2];
                    mma_bf16(cc, Ah, bh);
                    mma_bf16(cc, Ah, bl);
                    mma_bf16(cc, Al, bh);
                }
            }
        }
        __syncthreads();
    }

    __nv_bfloat16* OH = by ? d_Kh : d_Qh;
    __nv_bfloat16* OL = by ? d_Kl : d_Ql;
    #pragma unroll
    for (int mi = 0; mi < 2; mi++)
        #pragma unroll
        for (int nf = 0; nf < 4; nf++)
            #pragma unroll
            for (int hrow = 0; hrow < 2; hrow++) {
                int row = mbase + wm * 32 + mi * 16 + (lane >> 2) + 8 * hrow;
                int col = wn * 32 + nf * 8 + 2 * (lane & 3);
                float v0 = acc[mi][nf][2 * hrow]     + bias_s[col];
                float v1 = acc[mi][nf][2 * hrow + 1] + bias_s[col + 1];
                __nv_bfloat16 h0, l0, h1, l1;
                bf16_split(v0, h0, l0);
                bf16_split(v1, h1, l1);
                *(__nv_bfloat162*)(OH + (size_t)row * DK + col) = __nv_bfloat162(h0, h1);
                *(__nv_bfloat162*)(OL + (size_t)row * DK + col) = __nv_bfloat162(l0, l1);
            }
}

// ============================================================================
// attn: grid (32 qblocks, 4 chunks), 256 threads = 8 warps (2M x 4N),
// warp tile 64x32, ping-pong acc sets; epilogue(kt-1) interleaved into
// MMA(kt) dispatch (2 fragment-pairs per k-step). rk/fk in 4-slot ring.
// ============================================================================
#define SM_GATE  0          // 4096
#define SM_RK    4096       // float[4][128]
#define SM_FK    6144       // float[4][128]
#define SM_PL    8192       // float[4][128]
#define SM_PW    10240
#define SM_QH    12288      // 32768
#define SM_QL    45056
#define SM_KH    77824      // 2 x 32768
#define SM_KL    143360     // 2 x 32768
#define SMEM_TOTAL 208896

__device__ __forceinline__ void cp_tile(const __nv_bfloat16* __restrict__ g,
                                        uint32_t st_base) {
    int tid = threadIdx.x;
    #pragma unroll
    for (int i = 0; i < 8; i++) {
        int idx = tid + 256 * i;
        int row = idx >> 4, c = idx & 15;
        cp16(st_base + row * 256 + swz(c, row) * 16, (const char*)g + row * 256 + c * 16);
    }
}

__global__ void __launch_bounds__(256, 1) attn_kernel(const float* __restrict__ ranks) {
    extern __shared__ __align__(1024) char smem[];
    float* gate_s = (float*)(smem + SM_GATE);
    float* rk_s   = (float*)(smem + SM_RK);   // [4][128] ring
    float* fk_s   = (float*)(smem + SM_FK);
    float* pl_s   = (float*)(smem + SM_PL);
    float* pw_s   = (float*)(smem + SM_PW);
    uint32_t sb = smem_u32(smem);

    int tid = threadIdx.x;
    int w = tid >> 5, lane = tid & 31;
    int wm = w >> 2, wn = w & 3;          // 2 x 4 warp grid, warp tile 64x32
    int qbase = blockIdx.x * 128;
    int cbase = blockIdx.y * KEYS_PER_CHUNK;

    #pragma unroll
    for (int t = 0; t < 4; t++) gate_s[tid + 256 * t] = d_gate[tid + 256 * t];

    cp_tile(d_Qh + (size_t)qbase * DK, sb + SM_QH);
    cp_tile(d_Ql + (size_t)qbase * DK, sb + SM_QL);
    cp_tile(d_Kh + (size_t)cbase * DK, sb + SM_KH);
    cp_tile(d_Kl + (size_t)cbase * DK, sb + SM_KL);
    if (tid < 128) {
        cp4(sb + SM_RK + tid * 4, ranks + cbase + tid);
        cp4(sb + SM_FK + tid * 4, d_f + cbase + tid);
    }
    CP_COMMIT();

    // per-thread rows: slot s = mi*2+h -> row = wm*64 + (s>>1)*16 + (lane>>2) + 8h
    float rq_t[8];
    #pragma unroll
    for (int s = 0; s < 8; s++)
        rq_t[s] = ranks[qbase + wm * 64 + (s >> 1) * 16 + (lane >> 2) + 8 * (s & 1)];

    float l_t[8], w_t[8];
    #pragma unroll
    for (int s = 0; s < 8; s++) { l_t[s] = 0.f; w_t[s] = 0.f; }

    // two accumulator sets, 64 floats each: index (mi*4+nf)*4 + e
    float acc[2][64];
    #pragma unroll
    for (int ps = 0; ps < 2; ps++)
        #pragma unroll
        for (int e = 0; e < 64; e++) acc[ps][e] = 0.f;

    CP_WAIT0();
    __syncthreads();

    int a_row  = lane & 15, a_hi = lane >> 4;
    int b_nloc = (lane & 7) | ((lane >> 1) & 8);
    int b_hi   = (lane >> 3) & 1;
    int cqr = lane >> 2;       // epilogue col-lane components
    int ccl = 2 * (lane & 3);

    for (int kt = 0; kt < 8; kt++) {
        int set = kt & 1;
        uint32_t KHb = sb + SM_KH + set * 32768;
        uint32_t KLb = sb + SM_KL + set * 32768;

        if (kt < 7) {
            int kb = cbase + (kt + 1) * 128;
            int nb = (kt + 1) & 1, ns = (kt + 1) & 3;
            cp_tile(d_Kh + (size_t)kb * DK, sb + SM_KH + nb * 32768);
            cp_tile(d_Kl + (size_t)kb * DK, sb + SM_KL + nb * 32768);
            if (tid < 128) {
                cp4(sb + SM_RK + (ns * 128 + tid) * 4, ranks + kb + tid);
                cp4(sb + SM_FK + (ns * 128 + tid) * 4, d_f + kb + tid);
            }
            CP_COMMIT();
        }

        // rk/fk regs for epilogue(kt-1): ring slot (kt-1)&3 (never the prefetch slot)
        float rk_t[8], fk_t[8];
        if (kt > 0) {
            int es = (kt - 1) & 3;
            #pragma unroll
            for (int nf = 0; nf < 4; nf++)
                #pragma unroll
                for (int h = 0; h < 2; h++) {
                    int c = es * 128 + wn * 32 + nf * 8 + ccl + h;
                    rk_t[nf * 2 + h] = rk_s[c];
                    fk_t[nf * 2 + h] = fk_s[c];
                }
        }
        float* pacc = acc[set ^ 1];   // previous tile's accumulators
        float* cacc = acc[set];

        #pragma unroll
        for (int ks = 0; ks < 8; ks++) {
            // ---- MMA dispatch for this k-step ----
            uint32_t Bh[2][4], Bl[2][4];
            int cB = 2 * ks + b_hi;
            #pragma unroll
            for (int np = 0; np < 2; np++) {
                int nrow = wn * 32 + np * 16 + b_nloc;
                uint32_t off = nrow * 256 + swz(cB, nrow) * 16;
                ldsm4(Bh[np], KHb + off);
                ldsm4(Bl[np], KLb + off);
            }
            #pragma unroll
            for (int mi = 0; mi < 4; mi++) {
                uint32_t Ah[4], Al[4];
                int qrow = wm * 64 + mi * 16 + a_row;
                int cA = 2 * ks + a_hi;
                uint32_t off = qrow * 256 + swz(cA, qrow) * 16;
                ldsm4(Ah, sb + SM_QH + off);
                ldsm4(Al, sb + SM_QL + off);
                #pragma unroll
                for (int nf = 0; nf < 4; nf++) {
                    float* c = cacc + (mi * 4 + nf) * 4;
                    const uint32_t* bh = &Bh[nf >> 1][(nf & 1) * 2];
                    const uint32_t* bl = &Bl[nf >> 1][(nf & 1) * 2];
                    mma_bf16(c, Ah, bh);
                    mma_bf16(c, Ah, bl);
                    mma_bf16(c, Al, bh);
                }
            }
            // ---- interleaved epilogue: 2 fragment-pairs of tile kt-1 ----
            if (kt > 0) {
                #pragma unroll
                for (int pp = 0; pp < 2; pp++) {
                    int p = 2 * ks + pp;
                    int mi = p >> 2, nf = p & 3;
                    float* pa = pacc + (mi * 4 + nf) * 4;
                    #pragma unroll
                    for (int e = 0; e < 4; e++) {
                        int s = mi * 2 + (e >> 1);
                        int ci = nf * 2 + (e & 1);
                        int di = min(__float2int_rd(fabsf(rq_t[s] - rk_t[ci]) * 0.25f),
                                     NUM_EMB - 1);
                        float pr = exp2f(gate_s[di] * pa[e]);
                        l_t[s] += pr;
                        w_t[s] += pr * fk_t[ci];
                        pa[e] = 0.f;
                    }
                }
            }
        }

        CP_WAIT0();
        __syncthreads();
    }

    // ---- tail epilogue: tile 7 (set 1, ring slot 3) ----
    {
        float rk_t[8], fk_t[8];
        #pragma unroll
        for (int nf = 0; nf < 4; nf++)
            #pragma unroll
            for (int h = 0; h < 2; h++) {
                int c = 3 * 128 + wn * 32 + nf * 8 + ccl + h;
                rk_t[nf * 2 + h] = rk_s[c];
                fk_t[nf * 2 + h] = fk_s[c];
            }
        float* pa0 = acc[1];
        #pragma unroll
        for (int p = 0; p < 16; p++) {
            int mi = p >> 2, nf = p & 3;
            float* pa = pa0 + (mi * 4 + nf) * 4;
            #pragma unroll
            for (int e = 0; e < 4; e++) {
                int s = mi * 2 + (e >> 1);
                int ci = nf * 2 + (e & 1);
                int di = min(__float2int_rd(fabsf(rq_t[s] - rk_t[ci]) * 0.25f),
                             NUM_EMB - 1);
                float pr = exp2f(gate_s[di] * pa[e]);
                l_t[s] += pr;
                w_t[s] += pr * fk_t[ci];
            }
        }
    }

    // quad reduce (cols within warp), then across 4 N-warps via smem
    #pragma unroll
    for (int s = 0; s < 8; s++) {
        #pragma unroll
        for (int st = 1; st < 4; st <<= 1) {
            l_t[s] += __shfl_xor_sync(0xffffffffu, l_t[s], st);
            w_t[s] += __shfl_xor_sync(0xffffffffu, w_t[s], st);
        }
    }
    if ((lane & 3) == 0) {
        #pragma unroll
        for (int s = 0; s < 8; s++) {
            int row = wm * 64 + (s >> 1) * 16 + cqr + 8 * (s & 1);
            pl_s[wn * 128 + row] = l_t[s];
            pw_s[wn * 128 + row] = w_t[s];
        }
    }
    __syncthreads();
    if (tid < 128) {
        float L = 0.f, W = 0.f;
        #pragma unroll
        for (int k = 0; k < 4; k++) {
            L += pl_s[k * 128 + tid];
            W += pw_s[k * 128 + tid];
        }
        int idx = blockIdx.y * N_ASSETS + qbase + tid;
        d_pl[idx] = L;
        d_pw[idx] = W;
    }
}

// ============================================================================
// combine: merge NCHUNK partial sums, final sigmoid
// ============================================================================
__global__ void combine_kernel(const float* __restrict__ wf_b, float* __restrict__ out) {
    int i = blockIdx.x * blockDim.x + threadIdx.x;
    if (i >= N_ASSETS) return;
    float L = 0.f, W = 0.f;
    #pragma unroll
    for (int c = 0; c < NCHUNK; c++) {
        L += d_pl[c * N_ASSETS + i];
        W += d_pw[c * N_ASSETS + i];
    }
    float z = W / L + wf_b[0];
    out[i] = 1.0f / (1.0f + __expf(-z));
}

// ============================================================================
// launch
// ============================================================================
extern "C" void kernel_launch(void* const* d_in, const int* in_sizes, int n_in,
                              void* d_out, int out_size) {
    const float* S        = (const float*)d_in[0];
    const float* ranks    = (const float*)d_in[1];
    const float* Wq_w     = (const float*)d_in[2];
    const float* Wq_b     = (const float*)d_in[3];
    const float* Wk_w     = (const float*)d_in[4];
    const float* Wk_b     = (const float*)d_in[5];
    const float* Wv_w     = (const float*)d_in[6];
    const float* Wv_b     = (const float*)d_in[7];
    const float* rank_emb = (const float*)d_in[8];
    const float* wL_w     = (const float*)d_in[9];
    const float* wL_b     = (const float*)d_in[10];
    const float* wf_w     = (const float*)d_in[11];
    const float* wf_b     = (const float*)d_in[12];
    float* out = (float*)d_out;

    static int attr_set = 0;
    if (!attr_set) {
        cudaFuncSetAttribute(attn_kernel,
                             cudaFuncAttributeMaxDynamicSharedMemorySize, SMEM_TOTAL);
        cudaFuncSetAttribute(proj_mma_kernel,
                             cudaFuncAttributeMaxDynamicSharedMemorySize, PJ_TOTAL);
        attr_set = 1;
    }

    prep_kernel<<<85, 256>>>(rank_emb, wL_w, wL_b, Wv_w, wf_w, Wv_b, Wq_w, Wk_w);
    convS_kernel<<<128, 256>>>(S);
    proj_mma_kernel<<<dim3(64, 2), 256, PJ_TOTAL>>>(Wq_b, Wk_b);
    attn_kernel<<<dim3(32, NCHUNK), 256, SMEM_TOTAL>>>(ranks);
    combine_kernel<<<16, 256>>>(wf_b, out);
}

// round 9
// speedup vs baseline: 1.8333x; 1.8333x over previous
#include <cuda_runtime.h>
#include <cuda_bf16.h>
#include <cstdint>

// ============================================================================
// CAAN rank-gated attention (sm_100 base: mma.sync bf16 + cp.async):
//   Sh/Sl = bf16 split of S; f[i] = S[i].u + c (fused into convS)
//   Q,K   = S Wq^T/Wk^T via 3-product bf16-split HMMA, re-split to bf16 hi/lo
//   gate2[d] = log2(e)/sqrt(128) * sigmoid(rank_emb[d].wL+bL)
//   p_ij = exp2( gate2[|ri-rj|/4] * (q_i.k_j) )   (no-max softmax; |arg| small)
//   out_i = sigmoid( (sum_j p f_j)/(sum_j p) + wf_b )
// attn: 64-row Q blocks, 104KB smem, 2 CTAs/SM -> cross-CTA overlap of
// tensor phase and epilogue phase (no extra registers; R8's in-thread
// ping-pong spilled). K copy for tile kt+1 overlaps epilogue of tile kt.
// ============================================================================

#define N_ASSETS 4096
#define D_MODEL  512
#define DK       128
#define NUM_EMB  1024
#define NCHUNK   4
#define KEYS_PER_CHUNK (N_ASSETS / NCHUNK)
#define GATE_MUL    0.1275174677682657f      // (1/sqrt(128)) * log2(e)

typedef unsigned long long ull;

// --------------------------- scratch (no allocs) ----------------------------
__device__ __align__(16) __nv_bfloat16 d_Sh[N_ASSETS * D_MODEL];
__device__ __align__(16) __nv_bfloat16 d_Sl[N_ASSETS * D_MODEL];
__device__ __align__(16) __nv_bfloat16 d_Wh[256 * D_MODEL];   // rows 0-127 Wq, 128-255 Wk
__device__ __align__(16) __nv_bfloat16 d_Wl[256 * D_MODEL];
__device__ __align__(16) __nv_bfloat16 d_Qh[N_ASSETS * DK];
__device__ __align__(16) __nv_bfloat16 d_Ql[N_ASSETS * DK];
__device__ __align__(16) __nv_bfloat16 d_Kh[N_ASSETS * DK];
__device__ __align__(16) __nv_bfloat16 d_Kl[N_ASSETS * DK];
__device__ float d_f[N_ASSETS];
__device__ float d_u[D_MODEL + 1];
__device__ float d_gate[NUM_EMB];            // premultiplied by GATE_MUL
__device__ float d_pl[NCHUNK * N_ASSETS];
__device__ float d_pw[NCHUNK * N_ASSETS];

// --------------------------- mma/ldsm/cp.async helpers -----------------------
__device__ __forceinline__ uint32_t smem_u32(const void* p) {
    uint32_t a;
    asm("{ .reg .u64 t; cvta.to.shared.u64 t, %1; cvt.u32.u64 %0, t; }"
        : "=r"(a) : "l"(p));
    return a;
}
__device__ __forceinline__ void ldsm4(uint32_t* r, uint32_t addr) {
    asm volatile("ldmatrix.sync.aligned.m8n8.x4.shared.b16 {%0,%1,%2,%3}, [%4];"
                 : "=r"(r[0]), "=r"(r[1]), "=r"(r[2]), "=r"(r[3]) : "r"(addr));
}
__device__ __forceinline__ void mma_bf16(float* c, const uint32_t* a, const uint32_t* b) {
    asm volatile(
        "mma.sync.aligned.m16n8k16.row.col.f32.bf16.bf16.f32 "
        "{%0,%1,%2,%3}, {%4,%5,%6,%7}, {%8,%9}, {%0,%1,%2,%3};"
        : "+f"(c[0]), "+f"(c[1]), "+f"(c[2]), "+f"(c[3])
        : "r"(a[0]), "r"(a[1]), "r"(a[2]), "r"(a[3]), "r"(b[0]), "r"(b[1]));
}
__device__ __forceinline__ void cp16(uint32_t dst, const void* src) {
    asm volatile("cp.async.cg.shared.global [%0], [%1], 16;" :: "r"(dst), "l"(src));
}
__device__ __forceinline__ void cp4(uint32_t dst, const void* src) {
    asm volatile("cp.async.ca.shared.global [%0], [%1], 4;" :: "r"(dst), "l"(src));
}
#define CP_COMMIT() asm volatile("cp.async.commit_group;" ::: "memory")
#define CP_WAIT0()  asm volatile("cp.async.wait_group 0;" ::: "memory")
#define CP_WAIT1()  asm volatile("cp.async.wait_group 1;" ::: "memory")

// XOR swizzle of 16B-chunk index within a 256B row (16 chunks)
__device__ __forceinline__ int swz(int chunk, int row) {
    return (chunk & 8) | ((chunk ^ row) & 7);
}
__device__ __forceinline__ void bf16_split(float v, __nv_bfloat16& h, __nv_bfloat16& l) {
    h = __float2bfloat16(v);
    l = __float2bfloat16(v - __bfloat162float(h));
}

// ============================================================================
// prep: gate (b 0-3), u (b 4-19), c (b 20), W bf16 split (b 21-84)
// ============================================================================
__global__ void prep_kernel(const float* __restrict__ rank_emb,
                            const float* __restrict__ wL_w,
                            const float* __restrict__ wL_b,
                            const float* __restrict__ Wv_w,
                            const float* __restrict__ wf_w,
                            const float* __restrict__ Wv_b,
                            const float* __restrict__ Wq_w,
                            const float* __restrict__ Wk_w) {
    int b = blockIdx.x, t = threadIdx.x;
    if (b < 4) {
        int d = b * 256 + t;
        float s = wL_b[0];
        #pragma unroll 8
        for (int e = 0; e < 32; e++) s += rank_emb[d * 32 + e] * wL_w[e];
        d_gate[d] = GATE_MUL / (1.0f + __expf(-s));
    } else if (b < 20) {
        int b2 = b - 4;
        int mloc = t & 31, oo = t >> 5;
        int m = b2 * 32 + mloc;
        float s = 0.f;
        #pragma unroll 4
        for (int o = oo; o < D_MODEL; o += 8) s += Wv_w[o * D_MODEL + m] * wf_w[o];
        __shared__ float red[256];
        red[t] = s; __syncthreads();
        if (t < 32) {
            float x = red[t];
            #pragma unroll
            for (int i = 1; i < 8; i++) x += red[t + 32 * i];
            d_u[m] = x;
        }
    } else if (b == 20) {
        __shared__ float red[256];
        float s = 0.f;
        for (int o = t; o < D_MODEL; o += 256) s += wf_w[o] * Wv_b[o];
        red[t] = s; __syncthreads();
        for (int st = 128; st > 0; st >>= 1) {
            if (t < st) red[t] += red[t + st];
            __syncthreads();
        }
        if (t == 0) d_u[D_MODEL] = red[0];
    } else {
        int g0 = (b - 21) * 2048 + t * 8;
        #pragma unroll
        for (int j = 0; j < 2; j++) {
            float4 v = (g0 + 4 * j < 65536)
                ? *(const float4*)(Wq_w + g0 + 4 * j)
                : *(const float4*)(Wk_w + g0 + 4 * j - 65536);
            float vv[4] = {v.x, v.y, v.z, v.w};
            #pragma unroll
            for (int e = 0; e < 4; e++) {
                __nv_bfloat16 h, l;
                bf16_split(vv[e], h, l);
                d_Wh[g0 + 4 * j + e] = h;
                d_Wl[g0 + 4 * j + e] = l;
            }
        }
    }
}

// ============================================================================
// convS: split S into bf16 hi/lo AND compute f[i] = S[i].u + c (one pass)
// ============================================================================
__global__ void __launch_bounds__(256) convS_kernel(const float* __restrict__ S) {
    __shared__ float u_s[D_MODEL];
    int tid = threadIdx.x, w = tid >> 5, lane = tid & 31;
    #pragma unroll
    for (int t = 0; t < 2; t++) u_s[tid + 256 * t] = d_u[tid + 256 * t];
    __syncthreads();
    float c = d_u[D_MODEL];

    int rbase = blockIdx.x * 32 + w * 4;
    #pragma unroll
    for (int rr = 0; rr < 4; rr++) {
        int row = rbase + rr;
        const float2* src = (const float2*)(S + (size_t)row * D_MODEL);
        __nv_bfloat162* dh = (__nv_bfloat162*)(d_Sh + (size_t)row * D_MODEL);
        __nv_bfloat162* dl = (__nv_bfloat162*)(d_Sl + (size_t)row * D_MODEL);
        float s = 0.f;
        #pragma unroll
        for (int t = 0; t < 8; t++) {
            int e2 = lane + 32 * t;
            float2 v = src[e2];
            s += v.x * u_s[2 * e2] + v.y * u_s[2 * e2 + 1];
            __nv_bfloat16 h0, l0, h1, l1;
            bf16_split(v.x, h0, l0);
            bf16_split(v.y, h1, l1);
            dh[e2] = __nv_bfloat162(h0, h1);
            dl[e2] = __nv_bfloat162(l0, l1);
        }
        #pragma unroll
        for (int st = 16; st > 0; st >>= 1)
            s += __shfl_xor_sync(0xffffffffu, s, st);
        if (lane == 0) d_f[row] = s + c;
    }
}

// ============================================================================
// proj_mma: Q/K = S @ W^T + b via 3-product bf16 HMMA, double-buffered stages.
// grid (64 M-tiles of 64 rows, 2 = {Q,K}), 256 thr = 8 warps (2M x 4N).
// ============================================================================
#define PJ_BIAS 0           // 512B
#define PJ_STG  1024        // stage stride 98304: SH 16K | SL 16K | WH 32K | WL 32K
#define PJ_SH   0
#define PJ_SL   16384
#define PJ_WH   32768
#define PJ_WL   65536
#define PJ_TOTAL (1024 + 2 * 98304)

__device__ __forceinline__ void pj_copy_stage(uint32_t stg, int mbase, int by, int kc) {
    int tid = threadIdx.x;
    #pragma unroll
    for (int i = 0; i < 4; i++) {
        int idx = tid + 256 * i;
        int row = idx >> 4, c = idx & 15;
        const __nv_bfloat16* gh = d_Sh + (size_t)(mbase + row) * D_MODEL + kc * 128 + c * 8;
        cp16(stg + PJ_SH + row * 256 + swz(c, row) * 16, gh);
        const __nv_bfloat16* gl = d_Sl + (size_t)(mbase + row) * D_MODEL + kc * 128 + c * 8;
        cp16(stg + PJ_SL + row * 256 + swz(c, row) * 16, gl);
    }
    #pragma unroll
    for (int i = 0; i < 8; i++) {
        int idx = tid + 256 * i;
        int row = idx >> 4, c = idx & 15;
        const __nv_bfloat16* gh = d_Wh + (size_t)(by * 128 + row) * D_MODEL + kc * 128 + c * 8;
        cp16(stg + PJ_WH + row * 256 + swz(c, row) * 16, gh);
        const __nv_bfloat16* gl = d_Wl + (size_t)(by * 128 + row) * D_MODEL + kc * 128 + c * 8;
        cp16(stg + PJ_WL + row * 256 + swz(c, row) * 16, gl);
    }
}

__global__ void __launch_bounds__(256, 1) proj_mma_kernel(
    const float* __restrict__ Wq_b, const float* __restrict__ Wk_b) {
    extern __shared__ __align__(1024) char smem[];
    uint32_t sb = smem_u32(smem);
    float* bias_s = (float*)(smem + PJ_BIAS);

    int tid = threadIdx.x;
    int w = tid >> 5, lane = tid & 31;
    int wm = w >> 2, wn = w & 3;
    int mbase = blockIdx.x * 64;
    int by = blockIdx.y;                 // 0 = Q, 1 = K

    if (tid < 128) bias_s[tid] = (by ? Wk_b : Wq_b)[tid];

    float acc[2][4][4];
    #pragma unroll
    for (int mi = 0; mi < 2; mi++)
        #pragma unroll
        for (int nf = 0; nf < 4; nf++)
            #pragma unroll
            for (int e = 0; e < 4; e++) acc[mi][nf][e] = 0.f;

    int a_row  = lane & 15, a_hi = lane >> 4;
    int b_nloc = (lane & 7) | ((lane >> 1) & 8);
    int b_hi   = (lane >> 3) & 1;

    pj_copy_stage(sb + PJ_STG, mbase, by, 0);
    CP_COMMIT();

    for (int kc = 0; kc < 4; kc++) {
        uint32_t stg = sb + PJ_STG + (kc & 1) * 98304;
        if (kc < 3) {
            pj_copy_stage(sb + PJ_STG + ((kc + 1) & 1) * 98304, mbase, by, kc + 1);
            CP_COMMIT();
            CP_WAIT1();
        } else {
            CP_WAIT0();
        }
        __syncthreads();

        #pragma unroll
        for (int ks = 0; ks < 8; ks++) {
            uint32_t Bh[2][4], Bl[2][4];
            int cB = 2 * ks + b_hi;
            #pragma unroll
            for (int np = 0; np < 2; np++) {
                int nrow = wn * 32 + np * 16 + b_nloc;
                uint32_t off = nrow * 256 + swz(cB, nrow) * 16;
                ldsm4(Bh[np], stg + PJ_WH + off);
                ldsm4(Bl[np], stg + PJ_WL + off);
            }
            #pragma unroll
            for (int mi = 0; mi < 2; mi++) {
                uint32_t Ah[4], Al[4];
                int qrow = wm * 32 + mi * 16 + a_row;
                int cA = 2 * ks + a_hi;
                uint32_t off = qrow * 256 + swz(cA, qrow) * 16;
                ldsm4(Ah, stg + PJ_SH + off);
                ldsm4(Al, stg + PJ_SL + off);
                #pragma unroll
                for (int nf = 0; nf < 4; nf++) {
                    float* cc = acc[mi][nf];
                    const uint32_t* bh = &Bh[nf >> 1][(nf & 1) * 2];
                    const uint32_t* bl = &Bl[nf >> 1][(nf & 1) * 2];
                    mma_bf16(cc, Ah, bh);
                    mma_bf16(cc, Ah, bl);
                    mma_bf16(cc, Al, bh);
                }
            }
        }
        __syncthreads();
    }

    __nv_bfloat16* OH = by ? d_Kh : d_Qh;
    __nv_bfloat16* OL = by ? d_Kl : d_Ql;
    #pragma unroll
    for (int mi = 0; mi < 2; mi++)
        #pragma unroll
        for (int nf = 0; nf < 4; nf++)
            #pragma unroll
            for (int hrow = 0; hrow < 2; hrow++) {
                int row = mbase + wm * 32 + mi * 16 + (lane >> 2) + 8 * hrow;
                int col = wn * 32 + nf * 8 + 2 * (lane & 3);
                float v0 = acc[mi][nf][2 * hrow]     + bias_s[col];
                float v1 = acc[mi][nf][2 * hrow + 1] + bias_s[col + 1];
                __nv_bfloat16 h0, l0, h1, l1;
                bf16_split(v0, h0, l0);
                bf16_split(v1, h1, l1);
                *(__nv_bfloat162*)(OH + (size_t)row * DK + col) = __nv_bfloat162(h0, h1);
                *(__nv_bfloat162*)(OL + (size_t)row * DK + col) = __nv_bfloat162(l0, l1);
            }
}

// ============================================================================
// attn: grid (64 qblocks of 64 rows, 4 chunks), 256 thr = 8 warps (2M x 4N),
// warp tile 32x32, single acc set. ~104KB smem -> 2 CTAs/SM: epilogue of one
// CTA overlaps MMAs of the other. K single-buffered; next K copy issued
// between MMA loop and epilogue (K smem dead during epilogue).
// ============================================================================
#define SM_GATE  0          // 4096
#define SM_RK    4096       // float[2][128] ring
#define SM_FK    5120       // float[2][128]
#define SM_PL    6144       // float[4][64]
#define SM_PW    7168       // float[4][64]
#define SM_QH    8192       // 16384
#define SM_QL    24576      // 16384
#define SM_KH    40960      // 32768
#define SM_KL    73728      // 32768
#define SMEM_TOTAL 106496

__device__ __forceinline__ void cp_tile128(const __nv_bfloat16* __restrict__ g,
                                           uint32_t st_base) {
    int tid = threadIdx.x;
    #pragma unroll
    for (int i = 0; i < 8; i++) {
        int idx = tid + 256 * i;
        int row = idx >> 4, c = idx & 15;
        cp16(st_base + row * 256 + swz(c, row) * 16, (const char*)g + row * 256 + c * 16);
    }
}
__device__ __forceinline__ void cp_tile64(const __nv_bfloat16* __restrict__ g,
                                          uint32_t st_base) {
    int tid = threadIdx.x;
    #pragma unroll
    for (int i = 0; i < 4; i++) {
        int idx = tid + 256 * i;
        int row = idx >> 4, c = idx & 15;
        cp16(st_base + row * 256 + swz(c, row) * 16, (const char*)g + row * 256 + c * 16);
    }
}

__global__ void __launch_bounds__(256, 2) attn_kernel(const float* __restrict__ ranks) {
    extern __shared__ __align__(1024) char smem[];
    float* gate_s = (float*)(smem + SM_GATE);
    float* rk_s   = (float*)(smem + SM_RK);   // [2][128] ring
    float* fk_s   = (float*)(smem + SM_FK);
    float* pl_s   = (float*)(smem + SM_PL);   // [4][64]
    float* pw_s   = (float*)(smem + SM_PW);
    uint32_t sb = smem_u32(smem);

    int tid = threadIdx.x;
    int w = tid >> 5, lane = tid & 31;
    int wm = w >> 2, wn = w & 3;          // 2 x 4 warp grid, warp tile 32x32
    int qbase = blockIdx.x * 64;
    int cbase = blockIdx.y * KEYS_PER_CHUNK;

    #pragma unroll
    for (int t = 0; t < 4; t++) gate_s[tid + 256 * t] = d_gate[tid + 256 * t];

    cp_tile64(d_Qh + (size_t)qbase * DK, sb + SM_QH);
    cp_tile64(d_Ql + (size_t)qbase * DK, sb + SM_QL);
    cp_tile128(d_Kh + (size_t)cbase * DK, sb + SM_KH);
    cp_tile128(d_Kl + (size_t)cbase * DK, sb + SM_KL);
    if (tid < 128) {
        cp4(sb + SM_RK + tid * 4, ranks + cbase + tid);
        cp4(sb + SM_FK + tid * 4, d_f + cbase + tid);
    }
    CP_COMMIT();

    // per-thread rows: slot s -> row = wm*32 + (s>>1)*16 + (lane>>2) + 8*(s&1)
    float rq_t[4];
    #pragma unroll
    for (int s = 0; s < 4; s++)
        rq_t[s] = ranks[qbase + wm * 32 + (s >> 1) * 16 + (lane >> 2) + 8 * (s & 1)];

    float l_t[4], w_t[4];
    #pragma unroll
    for (int s = 0; s < 4; s++) { l_t[s] = 0.f; w_t[s] = 0.f; }

    float acc[2][4][4];
    #pragma unroll
    for (int mi = 0; mi < 2; mi++)
        #pragma unroll
        for (int nf = 0; nf < 4; nf++)
            #pragma unroll
            for (int e = 0; e < 4; e++) acc[mi][nf][e] = 0.f;

    int a_row  = lane & 15, a_hi = lane >> 4;
    int b_nloc = (lane & 7) | ((lane >> 1) & 8);
    int b_hi   = (lane >> 3) & 1;
    int ccl    = 2 * (lane & 3);

    for (int kt = 0; kt < 8; kt++) {
        CP_WAIT0();
        __syncthreads();          // K tile kt + rk/fk slot kt&1 ready

        // ---- MMA loop over k = 128 ----
        #pragma unroll
        for (int ks = 0; ks < 8; ks++) {
            uint32_t Bh[2][4], Bl[2][4];
            int cB = 2 * ks + b_hi;
            #pragma unroll
            for (int np = 0; np < 2; np++) {
                int nrow = wn * 32 + np * 16 + b_nloc;
                uint32_t off = nrow * 256 + swz(cB, nrow) * 16;
                ldsm4(Bh[np], sb + SM_KH + off);
                ldsm4(Bl[np], sb + SM_KL + off);
            }
            #pragma unroll
            for (int mi = 0; mi < 2; mi++) {
                uint32_t Ah[4], Al[4];
                int qrow = wm * 32 + mi * 16 + a_row;
                int cA = 2 * ks + a_hi;
                uint32_t off = qrow * 256 + swz(cA, qrow) * 16;
                ldsm4(Ah, sb + SM_QH + off);
                ldsm4(Al, sb + SM_QL + off);
                #pragma unroll
                for (int nf = 0; nf < 4; nf++) {
                    float* c = acc[mi][nf];
                    const uint32_t* bh = &Bh[nf >> 1][(nf & 1) * 2];
                    const uint32_t* bl = &Bl[nf >> 1][(nf & 1) * 2];
                    mma_bf16(c, Ah, bh);
                    mma_bf16(c, Ah, bl);
                    mma_bf16(c, Al, bh);
                }
            }
        }
        __syncthreads();          // all warps done reading K smem

        // ---- issue next K tile copy (overlaps epilogue below) ----
        if (kt < 7) {
            int kb = cbase + (kt + 1) * 128;
            int ns = (kt + 1) & 1;
            cp_tile128(d_Kh + (size_t)kb * DK, sb + SM_KH);
            cp_tile128(d_Kl + (size_t)kb * DK, sb + SM_KL);
            if (tid < 128) {
                cp4(sb + SM_RK + (ns * 128 + tid) * 4, ranks + kb + tid);
                cp4(sb + SM_FK + (ns * 128 + tid) * 4, d_f + kb + tid);
            }
            CP_COMMIT();
        }

        // ---- epilogue for tile kt (rk/fk ring slot kt&1) ----
        {
            int es = kt & 1;
            float rk_t[8], fk_t[8];
            #pragma unroll
            for (int nf = 0; nf < 4; nf++)
                #pragma unroll
                for (int h = 0; h < 2; h++) {
                    int c = es * 128 + wn * 32 + nf * 8 + ccl + h;
                    rk_t[nf * 2 + h] = rk_s[c];
                    fk_t[nf * 2 + h] = fk_s[c];
                }
            #pragma unroll
            for (int mi = 0; mi < 2; mi++)
                #pragma unroll
                for (int nf = 0; nf < 4; nf++)
                    #pragma unroll
                    for (int e = 0; e < 4; e++) {
                        int s = mi * 2 + (e >> 1);
                        int ci = nf * 2 + (e & 1);
                        int di = min(__float2int_rd(fabsf(rq_t[s] - rk_t[ci]) * 0.25f),
                                     NUM_EMB - 1);
                        float pr = exp2f(gate_s[di] * acc[mi][nf][e]);
                        l_t[s] += pr;
                        w_t[s] += pr * fk_t[ci];
                        acc[mi][nf][e] = 0.f;
                    }
        }
    }

    // quad reduce (cols within warp), then across 4 N-warps via smem
    #pragma unroll
    for (int s = 0; s < 4; s++) {
        #pragma unroll
        for (int st = 1; st < 4; st <<= 1) {
            l_t[s] += __shfl_xor_sync(0xffffffffu, l_t[s], st);
            w_t[s] += __shfl_xor_sync(0xffffffffu, w_t[s], st);
        }
    }
    if ((lane & 3) == 0) {
        #pragma unroll
        for (int s = 0; s < 4; s++) {
            int row = wm * 32 + (s >> 1) * 16 + (lane >> 2) + 8 * (s & 1);
            pl_s[wn * 64 + row] = l_t[s];
            pw_s[wn * 64 + row] = w_t[s];
        }
    }
    __syncthreads();
    if (tid < 64) {
        float L = 0.f, W = 0.f;
        #pragma unroll
        for (int k = 0; k < 4; k++) {
            L += pl_s[k * 64 + tid];
            W += pw_s[k * 64 + tid];
        }
        int idx = blockIdx.y * N_ASSETS + qbase + tid;
        d_pl[idx] = L;
        d_pw[idx] = W;
    }
}

// ============================================================================
// combine: merge NCHUNK partial sums, final sigmoid
// ============================================================================
__global__ void combine_kernel(const float* __restrict__ wf_b, float* __restrict__ out) {
    int i = blockIdx.x * blockDim.x + threadIdx.x;
    if (i >= N_ASSETS) return;
    float L = 0.f, W = 0.f;
    #pragma unroll
    for (int c = 0; c < NCHUNK; c++) {
        L += d_pl[c * N_ASSETS + i];
        W += d_pw[c * N_ASSETS + i];
    }
    float z = W / L + wf_b[0];
    out[i] = 1.0f / (1.0f + __expf(-z));
}

// ============================================================================
// launch
// ============================================================================
extern "C" void kernel_launch(void* const* d_in, const int* in_sizes, int n_in,
                              void* d_out, int out_size) {
    const float* S        = (const float*)d_in[0];
    const float* ranks    = (const float*)d_in[1];
    const float* Wq_w     = (const float*)d_in[2];
    const float* Wq_b     = (const float*)d_in[3];
    const float* Wk_w     = (const float*)d_in[4];
    const float* Wk_b     = (const float*)d_in[5];
    const float* Wv_w     = (const float*)d_in[6];
    const float* Wv_b     = (const float*)d_in[7];
    const float* rank_emb = (const float*)d_in[8];
    const float* wL_w     = (const float*)d_in[9];
    const float* wL_b     = (const float*)d_in[10];
    const float* wf_w     = (const float*)d_in[11];
    const float* wf_b     = (const float*)d_in[12];
    float* out = (float*)d_out;

    static int attr_set = 0;
    if (!attr_set) {
        cudaFuncSetAttribute(attn_kernel,
                             cudaFuncAttributeMaxDynamicSharedMemorySize, SMEM_TOTAL);
        cudaFuncSetAttribute(proj_mma_kernel,
                             cudaFuncAttributeMaxDynamicSharedMemorySize, PJ_TOTAL);
        attr_set = 1;
    }

    prep_kernel<<<85, 256>>>(rank_emb, wL_w, wL_b, Wv_w, wf_w, Wv_b, Wq_w, Wk_w);
    convS_kernel<<<128, 256>>>(S);
    proj_mma_kernel<<<dim3(64, 2), 256, PJ_TOTAL>>>(Wq_b, Wk_b);
    attn_kernel<<<dim3(64, NCHUNK), 256, SMEM_TOTAL>>>(ranks);
    combine_kernel<<<16, 256>>>(wf_b, out);
}

// round 10
// speedup vs baseline: 2.9873x; 1.6294x over previous
#include <cuda_runtime.h>
#include <cuda_fp16.h>
#include <cstdint>

// ============================================================================
// CAAN rank-gated attention (sm_100 base: mma.sync fp16 + cp.async):
//   Sf = fp16(S); f[i] = S[i].u + c (fused into convS, fp32)
//   Q,K = fp16( S Wq^T/Wk^T + b )  via single-product fp16 HMMA
//   gate2[d] = log2(e)/sqrt(128) * sigmoid(rank_emb[d].wL+bL)
//   p_ij = exp2( gate2[|ri-rj|/4] * (q_i.k_j) )   (no-max softmax; |arg| small)
//   out_i = sigmoid( (sum_j p f_j)/(sum_j p) + wf_b )
// R9 post-mortem: attn pinned at ~46us & tensor~50% across 3 occupancy
// configs => legacy mma.sync throughput ceiling. Fix: fp16 single-product
// (3x fewer MACs; fp16's 11-bit mantissa keeps final err ~1e-5 << 1e-3).
// ============================================================================

#define N_ASSETS 4096
#define D_MODEL  512
#define DK       128
#define NUM_EMB  1024
#define NCHUNK   4
#define KEYS_PER_CHUNK (N_ASSETS / NCHUNK)
#define GATE_MUL    0.1275174677682657f      // (1/sqrt(128)) * log2(e)

typedef unsigned long long ull;

// --------------------------- scratch (no allocs) ----------------------------
__device__ __align__(16) __half d_Sf[N_ASSETS * D_MODEL];
__device__ __align__(16) __half d_Wf[256 * D_MODEL];   // rows 0-127 Wq, 128-255 Wk
__device__ __align__(16) __half d_Q[N_ASSETS * DK];
__device__ __align__(16) __half d_K[N_ASSETS * DK];
__device__ float d_f[N_ASSETS];
__device__ float d_u[D_MODEL + 1];
__device__ float d_gate[NUM_EMB];            // premultiplied by GATE_MUL
__device__ float d_pl[NCHUNK * N_ASSETS];
__device__ float d_pw[NCHUNK * N_ASSETS];

// --------------------------- mma/ldsm/cp.async helpers -----------------------
__device__ __forceinline__ uint32_t smem_u32(const void* p) {
    uint32_t a;
    asm("{ .reg .u64 t; cvta.to.shared.u64 t, %1; cvt.u32.u64 %0, t; }"
        : "=r"(a) : "l"(p));
    return a;
}
__device__ __forceinline__ void ldsm4(uint32_t* r, uint32_t addr) {
    asm volatile("ldmatrix.sync.aligned.m8n8.x4.shared.b16 {%0,%1,%2,%3}, [%4];"
                 : "=r"(r[0]), "=r"(r[1]), "=r"(r[2]), "=r"(r[3]) : "r"(addr));
}
__device__ __forceinline__ void mma_f16(float* c, const uint32_t* a, const uint32_t* b) {
    asm volatile(
        "mma.sync.aligned.m16n8k16.row.col.f32.f16.f16.f32 "
        "{%0,%1,%2,%3}, {%4,%5,%6,%7}, {%8,%9}, {%0,%1,%2,%3};"
        : "+f"(c[0]), "+f"(c[1]), "+f"(c[2]), "+f"(c[3])
        : "r"(a[0]), "r"(a[1]), "r"(a[2]), "r"(a[3]), "r"(b[0]), "r"(b[1]));
}
__device__ __forceinline__ void cp16(uint32_t dst, const void* src) {
    asm volatile("cp.async.cg.shared.global [%0], [%1], 16;" :: "r"(dst), "l"(src));
}
__device__ __forceinline__ void cp4(uint32_t dst, const void* src) {
    asm volatile("cp.async.ca.shared.global [%0], [%1], 4;" :: "r"(dst), "l"(src));
}
#define CP_COMMIT() asm volatile("cp.async.commit_group;" ::: "memory")
#define CP_WAIT0()  asm volatile("cp.async.wait_group 0;" ::: "memory")
#define CP_WAIT1()  asm volatile("cp.async.wait_group 1;" ::: "memory")

// XOR swizzle of 16B-chunk index within a 256B row (16 chunks)
__device__ __forceinline__ int swz(int chunk, int row) {
    return (chunk & 8) | ((chunk ^ row) & 7);
}

// ============================================================================
// prep: gate (b 0-3), u (b 4-19), c (b 20), W fp16 convert (b 21-84)
// ============================================================================
__global__ void prep_kernel(const float* __restrict__ rank_emb,
                            const float* __restrict__ wL_w,
                            const float* __restrict__ wL_b,
                            const float* __restrict__ Wv_w,
                            const float* __restrict__ wf_w,
                            const float* __restrict__ Wv_b,
                            const float* __restrict__ Wq_w,
                            const float* __restrict__ Wk_w) {
    int b = blockIdx.x, t = threadIdx.x;
    if (b < 4) {
        int d = b * 256 + t;
        float s = wL_b[0];
        #pragma unroll 8
        for (int e = 0; e < 32; e++) s += rank_emb[d * 32 + e] * wL_w[e];
        d_gate[d] = GATE_MUL / (1.0f + __expf(-s));
    } else if (b < 20) {
        int b2 = b - 4;
        int mloc = t & 31, oo = t >> 5;
        int m = b2 * 32 + mloc;
        float s = 0.f;
        #pragma unroll 4
        for (int o = oo; o < D_MODEL; o += 8) s += Wv_w[o * D_MODEL + m] * wf_w[o];
        __shared__ float red[256];
        red[t] = s; __syncthreads();
        if (t < 32) {
            float x = red[t];
            #pragma unroll
            for (int i = 1; i < 8; i++) x += red[t + 32 * i];
            d_u[m] = x;
        }
    } else if (b == 20) {
        __shared__ float red[256];
        float s = 0.f;
        for (int o = t; o < D_MODEL; o += 256) s += wf_w[o] * Wv_b[o];
        red[t] = s; __syncthreads();
        for (int st = 128; st > 0; st >>= 1) {
            if (t < st) red[t] += red[t + st];
            __syncthreads();
        }
        if (t == 0) d_u[D_MODEL] = red[0];
    } else {
        // W fp16 convert: 64 blocks x 256 thr x 8 elems = 131072 = 256*512
        int g0 = (b - 21) * 2048 + t * 8;
        #pragma unroll
        for (int j = 0; j < 2; j++) {
            float4 v = (g0 + 4 * j < 65536)
                ? *(const float4*)(Wq_w + g0 + 4 * j)
                : *(const float4*)(Wk_w + g0 + 4 * j - 65536);
            __half2* dst = (__half2*)(d_Wf + g0 + 4 * j);
            dst[0] = __floats2half2_rn(v.x, v.y);
            dst[1] = __floats2half2_rn(v.z, v.w);
        }
    }
}

// ============================================================================
// convS: S -> fp16 AND f[i] = S[i].u + c (one pass)
// ============================================================================
__global__ void __launch_bounds__(256) convS_kernel(const float* __restrict__ S) {
    __shared__ float u_s[D_MODEL];
    int tid = threadIdx.x, w = tid >> 5, lane = tid & 31;
    #pragma unroll
    for (int t = 0; t < 2; t++) u_s[tid + 256 * t] = d_u[tid + 256 * t];
    __syncthreads();
    float c = d_u[D_MODEL];

    int rbase = blockIdx.x * 32 + w * 4;
    #pragma unroll
    for (int rr = 0; rr < 4; rr++) {
        int row = rbase + rr;
        const float2* src = (const float2*)(S + (size_t)row * D_MODEL);
        __half2* dst = (__half2*)(d_Sf + (size_t)row * D_MODEL);
        float s = 0.f;
        #pragma unroll
        for (int t = 0; t < 8; t++) {
            int e2 = lane + 32 * t;
            float2 v = src[e2];
            s += v.x * u_s[2 * e2] + v.y * u_s[2 * e2 + 1];
            dst[e2] = __floats2half2_rn(v.x, v.y);
        }
        #pragma unroll
        for (int st = 16; st > 0; st >>= 1)
            s += __shfl_xor_sync(0xffffffffu, s, st);
        if (lane == 0) d_f[row] = s + c;
    }
}

// ============================================================================
// proj_mma: Q/K = fp16( S @ W^T + b ) single-product fp16 HMMA, 2-stage pipe.
// grid (64 M-tiles of 64 rows, 2 = {Q,K}), 256 thr = 8 warps (2M x 4N).
// ============================================================================
#define PJ_BIAS 0           // 512B
#define PJ_STG  1024        // stage stride 49152: S 16K | W 32K
#define PJ_S    0
#define PJ_W    16384
#define PJ_TOTAL (1024 + 2 * 49152)

__device__ __forceinline__ void pj_copy_stage(uint32_t stg, int mbase, int by, int kc) {
    int tid = threadIdx.x;
    // S: 64 rows x 128 fp16 cols (1024 chunks)
    #pragma unroll
    for (int i = 0; i < 4; i++) {
        int idx = tid + 256 * i;
        int row = idx >> 4, c = idx & 15;
        const __half* g = d_Sf + (size_t)(mbase + row) * D_MODEL + kc * 128 + c * 8;
        cp16(stg + PJ_S + row * 256 + swz(c, row) * 16, g);
    }
    // W: 128 rows x 128 fp16 cols (2048 chunks)
    #pragma unroll
    for (int i = 0; i < 8; i++) {
        int idx = tid + 256 * i;
        int row = idx >> 4, c = idx & 15;
        const __half* g = d_Wf + (size_t)(by * 128 + row) * D_MODEL + kc * 128 + c * 8;
        cp16(stg + PJ_W + row * 256 + swz(c, row) * 16, g);
    }
}

__global__ void __launch_bounds__(256, 1) proj_mma_kernel(
    const float* __restrict__ Wq_b, const float* __restrict__ Wk_b) {
    extern __shared__ __align__(1024) char smem[];
    uint32_t sb = smem_u32(smem);
    float* bias_s = (float*)(smem + PJ_BIAS);

    int tid = threadIdx.x;
    int w = tid >> 5, lane = tid & 31;
    int wm = w >> 2, wn = w & 3;
    int mbase = blockIdx.x * 64;
    int by = blockIdx.y;                 // 0 = Q, 1 = K

    if (tid < 128) bias_s[tid] = (by ? Wk_b : Wq_b)[tid];

    float acc[2][4][4];
    #pragma unroll
    for (int mi = 0; mi < 2; mi++)
        #pragma unroll
        for (int nf = 0; nf < 4; nf++)
            #pragma unroll
            for (int e = 0; e < 4; e++) acc[mi][nf][e] = 0.f;

    int a_row  = lane & 15, a_hi = lane >> 4;
    int b_nloc = (lane & 7) | ((lane >> 1) & 8);
    int b_hi   = (lane >> 3) & 1;

    pj_copy_stage(sb + PJ_STG, mbase, by, 0);
    CP_COMMIT();

    for (int kc = 0; kc < 4; kc++) {
        uint32_t stg = sb + PJ_STG + (kc & 1) * 49152;
        if (kc < 3) {
            pj_copy_stage(sb + PJ_STG + ((kc + 1) & 1) * 49152, mbase, by, kc + 1);
            CP_COMMIT();
            CP_WAIT1();
        } else {
            CP_WAIT0();
        }
        __syncthreads();

        #pragma unroll
        for (int ks = 0; ks < 8; ks++) {
            uint32_t Bf[2][4];
            int cB = 2 * ks + b_hi;
            #pragma unroll
            for (int np = 0; np < 2; np++) {
                int nrow = wn * 32 + np * 16 + b_nloc;
                ldsm4(Bf[np], stg + PJ_W + nrow * 256 + swz(cB, nrow) * 16);
            }
            #pragma unroll
            for (int mi = 0; mi < 2; mi++) {
                uint32_t Af[4];
                int qrow = wm * 32 + mi * 16 + a_row;
                int cA = 2 * ks + a_hi;
                ldsm4(Af, stg + PJ_S + qrow * 256 + swz(cA, qrow) * 16);
                #pragma unroll
                for (int nf = 0; nf < 4; nf++)
                    mma_f16(acc[mi][nf], Af, &Bf[nf >> 1][(nf & 1) * 2]);
            }
        }
        __syncthreads();
    }

    __half* OUT = by ? d_K : d_Q;
    #pragma unroll
    for (int mi = 0; mi < 2; mi++)
        #pragma unroll
        for (int nf = 0; nf < 4; nf++)
            #pragma unroll
            for (int hrow = 0; hrow < 2; hrow++) {
                int row = mbase + wm * 32 + mi * 16 + (lane >> 2) + 8 * hrow;
                int col = wn * 32 + nf * 8 + 2 * (lane & 3);
                float v0 = acc[mi][nf][2 * hrow]     + bias_s[col];
                float v1 = acc[mi][nf][2 * hrow + 1] + bias_s[col + 1];
                *(__half2*)(OUT + (size_t)row * DK + col) = __floats2half2_rn(v0, v1);
            }
}

// ============================================================================
// attn: grid (64 qblocks of 64 rows, 4 chunks), 256 thr = 8 warps (2M x 4N),
// warp tile 32x32, fp16 single-product. ~88KB smem -> 2 CTAs/SM; K tiles
// double-buffered so copies overlap MMA+epilogue.
// ============================================================================
#define SM_GATE  0          // 4096
#define SM_RK    4096       // float[2][128] ring
#define SM_FK    5120
#define SM_PL    6144       // float[4][64]
#define SM_PW    7168
#define SM_Q     8192       // 16384
#define SM_K     24576      // 2 x 32768
#define SMEM_TOTAL 90112

__device__ __forceinline__ void cp_tile128(const __half* __restrict__ g,
                                           uint32_t st_base) {
    int tid = threadIdx.x;
    #pragma unroll
    for (int i = 0; i < 8; i++) {
        int idx = tid + 256 * i;
        int row = idx >> 4, c = idx & 15;
        cp16(st_base + row * 256 + swz(c, row) * 16, (const char*)g + row * 256 + c * 16);
    }
}
__device__ __forceinline__ void cp_tile64(const __half* __restrict__ g,
                                          uint32_t st_base) {
    int tid = threadIdx.x;
    #pragma unroll
    for (int i = 0; i < 4; i++) {
        int idx = tid + 256 * i;
        int row = idx >> 4, c = idx & 15;
        cp16(st_base + row * 256 + swz(c, row) * 16, (const char*)g + row * 256 + c * 16);
    }
}

__global__ void __launch_bounds__(256, 2) attn_kernel(const float* __restrict__ ranks) {
    extern __shared__ __align__(1024) char smem[];
    float* gate_s = (float*)(smem + SM_GATE);
    float* rk_s   = (float*)(smem + SM_RK);   // [2][128] ring
    float* fk_s   = (float*)(smem + SM_FK);
    float* pl_s   = (float*)(smem + SM_PL);   // [4][64]
    float* pw_s   = (float*)(smem + SM_PW);
    uint32_t sb = smem_u32(smem);

    int tid = threadIdx.x;
    int w = tid >> 5, lane = tid & 31;
    int wm = w >> 2, wn = w & 3;          // 2 x 4 warp grid, warp tile 32x32
    int qbase = blockIdx.x * 64;
    int cbase = blockIdx.y * KEYS_PER_CHUNK;

    #pragma unroll
    for (int t = 0; t < 4; t++) gate_s[tid + 256 * t] = d_gate[tid + 256 * t];

    cp_tile64(d_Q + (size_t)qbase * DK, sb + SM_Q);
    cp_tile128(d_K + (size_t)cbase * DK, sb + SM_K);
    if (tid < 128) {
        cp4(sb + SM_RK + tid * 4, ranks + cbase + tid);
        cp4(sb + SM_FK + tid * 4, d_f + cbase + tid);
    }
    CP_COMMIT();

    // per-thread rows: slot s -> row = wm*32 + (s>>1)*16 + (lane>>2) + 8*(s&1)
    float rq_t[4];
    #pragma unroll
    for (int s = 0; s < 4; s++)
        rq_t[s] = ranks[qbase + wm * 32 + (s >> 1) * 16 + (lane >> 2) + 8 * (s & 1)];

    float l_t[4], w_t[4];
    #pragma unroll
    for (int s = 0; s < 4; s++) { l_t[s] = 0.f; w_t[s] = 0.f; }

    float acc[2][4][4];
    #pragma unroll
    for (int mi = 0; mi < 2; mi++)
        #pragma unroll
        for (int nf = 0; nf < 4; nf++)
            #pragma unroll
            for (int e = 0; e < 4; e++) acc[mi][nf][e] = 0.f;

    int a_row  = lane & 15, a_hi = lane >> 4;
    int b_nloc = (lane & 7) | ((lane >> 1) & 8);
    int b_hi   = (lane >> 3) & 1;
    int ccl    = 2 * (lane & 3);

    CP_WAIT0();
    __syncthreads();

    for (int kt = 0; kt < 8; kt++) {
        int buf = kt & 1;
        uint32_t Kb = sb + SM_K + buf * 32768;

        // prefetch next K tile into other buffer (overlaps MMA + epilogue)
        if (kt < 7) {
            int kb = cbase + (kt + 1) * 128;
            int nb = buf ^ 1;
            cp_tile128(d_K + (size_t)kb * DK, sb + SM_K + nb * 32768);
            if (tid < 128) {
                cp4(sb + SM_RK + (nb * 128 + tid) * 4, ranks + kb + tid);
                cp4(sb + SM_FK + (nb * 128 + tid) * 4, d_f + kb + tid);
            }
            CP_COMMIT();
        }

        // ---- MMA loop over k = 128 (single fp16 product) ----
        #pragma unroll
        for (int ks = 0; ks < 8; ks++) {
            uint32_t Bf[2][4];
            int cB = 2 * ks + b_hi;
            #pragma unroll
            for (int np = 0; np < 2; np++) {
                int nrow = wn * 32 + np * 16 + b_nloc;
                ldsm4(Bf[np], Kb + nrow * 256 + swz(cB, nrow) * 16);
            }
            #pragma unroll
            for (int mi = 0; mi < 2; mi++) {
                uint32_t Af[4];
                int qrow = wm * 32 + mi * 16 + a_row;
                int cA = 2 * ks + a_hi;
                ldsm4(Af, sb + SM_Q + qrow * 256 + swz(cA, qrow) * 16);
                #pragma unroll
                for (int nf = 0; nf < 4; nf++)
                    mma_f16(acc[mi][nf], Af, &Bf[nf >> 1][(nf & 1) * 2]);
            }
        }

        // ---- epilogue for tile kt (rk/fk ring slot kt&1) ----
        {
            int es = kt & 1;
            float rk_t[8], fk_t[8];
            #pragma unroll
            for (int nf = 0; nf < 4; nf++)
                #pragma unroll
                for (int h = 0; h < 2; h++) {
                    int c = es * 128 + wn * 32 + nf * 8 + ccl + h;
                    rk_t[nf * 2 + h] = rk_s[c];
                    fk_t[nf * 2 + h] = fk_s[c];
                }
            #pragma unroll
            for (int mi = 0; mi < 2; mi++)
                #pragma unroll
                for (int nf = 0; nf < 4; nf++)
                    #pragma unroll
                    for (int e = 0; e < 4; e++) {
                        int s = mi * 2 + (e >> 1);
                        int ci = nf * 2 + (e & 1);
                        int di = min(__float2int_rd(fabsf(rq_t[s] - rk_t[ci]) * 0.25f),
                                     NUM_EMB - 1);
                        float pr = exp2f(gate_s[di] * acc[mi][nf][e]);
                        l_t[s] += pr;
                        w_t[s] += pr * fk_t[ci];
                        acc[mi][nf][e] = 0.f;
                    }
        }

        CP_WAIT0();
        __syncthreads();
    }

    // quad reduce (cols within warp), then across 4 N-warps via smem
    #pragma unroll
    for (int s = 0; s < 4; s++) {
        #pragma unroll
        for (int st = 1; st < 4; st <<= 1) {
            l_t[s] += __shfl_xor_sync(0xffffffffu, l_t[s], st);
            w_t[s] += __shfl_xor_sync(0xffffffffu, w_t[s], st);
        }
    }
    if ((lane & 3) == 0) {
        #pragma unroll
        for (int s = 0; s < 4; s++) {
            int row = wm * 32 + (s >> 1) * 16 + (lane >> 2) + 8 * (s & 1);
            pl_s[wn * 64 + row] = l_t[s];
            pw_s[wn * 64 + row] = w_t[s];
        }
    }
    __syncthreads();
    if (tid < 64) {
        float L = 0.f, W = 0.f;
        #pragma unroll
        for (int k = 0; k < 4; k++) {
            L += pl_s[k * 64 + tid];
            W += pw_s[k * 64 + tid];
        }
        int idx = blockIdx.y * N_ASSETS + qbase + tid;
        d_pl[idx] = L;
        d_pw[idx] = W;
    }
}

// ============================================================================
// combine: merge NCHUNK partial sums, final sigmoid
// ============================================================================
__global__ void combine_kernel(const float* __restrict__ wf_b, float* __restrict__ out) {
    int i = blockIdx.x * blockDim.x + threadIdx.x;
    if (i >= N_ASSETS) return;
    float L = 0.f, W = 0.f;
    #pragma unroll
    for (int c = 0; c < NCHUNK; c++) {
        L += d_pl[c * N_ASSETS + i];
        W += d_pw[c * N_ASSETS + i];
    }
    float z = W / L + wf_b[0];
    out[i] = 1.0f / (1.0f + __expf(-z));
}

// ============================================================================
// launch
// ============================================================================
extern "C" void kernel_launch(void* const* d_in, const int* in_sizes, int n_in,
                              void* d_out, int out_size) {
    const float* S        = (const float*)d_in[0];
    const float* ranks    = (const float*)d_in[1];
    const float* Wq_w     = (const float*)d_in[2];
    const float* Wq_b     = (const float*)d_in[3];
    const float* Wk_w     = (const float*)d_in[4];
    const float* Wk_b     = (const float*)d_in[5];
    const float* Wv_w     = (const float*)d_in[6];
    const float* Wv_b     = (const float*)d_in[7];
    const float* rank_emb = (const float*)d_in[8];
    const float* wL_w     = (const float*)d_in[9];
    const float* wL_b     = (const float*)d_in[10];
    const float* wf_w     = (const float*)d_in[11];
    const float* wf_b     = (const float*)d_in[12];
    float* out = (float*)d_out;

    static int attr_set = 0;
    if (!attr_set) {
        cudaFuncSetAttribute(attn_kernel,
                             cudaFuncAttributeMaxDynamicSharedMemorySize, SMEM_TOTAL);
        cudaFuncSetAttribute(proj_mma_kernel,
                             cudaFuncAttributeMaxDynamicSharedMemorySize, PJ_TOTAL);
        attr_set = 1;
    }

    prep_kernel<<<85, 256>>>(rank_emb, wL_w, wL_b, Wv_w, wf_w, Wv_b, Wq_w, Wk_w);
    convS_kernel<<<128, 256>>>(S);
    proj_mma_kernel<<<dim3(64, 2), 256, PJ_TOTAL>>>(Wq_b, Wk_b);
    attn_kernel<<<dim3(64, NCHUNK), 256, SMEM_TOTAL>>>(ranks);
    combine_kernel<<<16, 256>>>(wf_b, out);
}